// round 4
// baseline (speedup 1.0000x reference)
#include <cuda_runtime.h>
#include <math.h>

#define B_SZ 4096
#define DIM  1024
#define GAMMA_S 0.8f
#define GAMMA_U 0.8f
#define RHO     0.1f
#define EPSV    1e-10f
#define TAU_MINV 0.005f
#define TAU_MAXV 1.0f
#define GRAD_CLIP 5.0f
#define ETA_INIT 0.01f
#define ETA_MINV 0.0001f

// 64MB scratch for the similarity matrix + per-row/col loss scratch.
__device__ float g_sim[B_SZ * B_SZ];
__device__ float g_loss_I[B_SZ];
__device__ float g_loss_T[B_SZ];

__device__ __forceinline__ float warpMax(float v) {
#pragma unroll
    for (int o = 16; o > 0; o >>= 1) v = fmaxf(v, __shfl_xor_sync(0xffffffffu, v, o));
    return v;
}
__device__ __forceinline__ float warpSum(float v) {
#pragma unroll
    for (int o = 16; o > 0; o >>= 1) v += __shfl_xor_sync(0xffffffffu, v, o);
    return v;
}

// ---------------------------------------------------------------------------
// GEMM: g_sim[i][j] = sum_d A[i][d] * B[j][d]   (both row-major [4096][1024])
// 128x128 block tile, BK=8, 256 threads, 8x8 per-thread microtile.
// ---------------------------------------------------------------------------
__global__ __launch_bounds__(256) void gemm_kernel(const float* __restrict__ A,
                                                   const float* __restrict__ Bm) {
    __shared__ float As[8][128];
    __shared__ float Bs[8][128];

    const int m0 = blockIdx.y * 128;
    const int n0 = blockIdx.x * 128;
    const int t  = threadIdx.x;
    const int tx = t & 15;       // 0..15 -> output cols tx*8..tx*8+7
    const int ty = t >> 4;       // 0..15 -> output rows ty*8..ty*8+7
    const int lrow = t >> 1;     // 0..127
    const int lcol = (t & 1) << 2; // 0 or 4

    const float* Ap = A  + (size_t)(m0 + lrow) * DIM + lcol;
    const float* Bp = Bm + (size_t)(n0 + lrow) * DIM + lcol;

    float acc[8][8];
#pragma unroll
    for (int i = 0; i < 8; i++)
#pragma unroll
        for (int j = 0; j < 8; j++) acc[i][j] = 0.0f;

    for (int k0 = 0; k0 < DIM; k0 += 8) {
        float4 av = *(const float4*)(Ap + k0);
        float4 bv = *(const float4*)(Bp + k0);
        As[lcol + 0][lrow] = av.x; As[lcol + 1][lrow] = av.y;
        As[lcol + 2][lrow] = av.z; As[lcol + 3][lrow] = av.w;
        Bs[lcol + 0][lrow] = bv.x; Bs[lcol + 1][lrow] = bv.y;
        Bs[lcol + 2][lrow] = bv.z; Bs[lcol + 3][lrow] = bv.w;
        __syncthreads();
#pragma unroll
        for (int kk = 0; kk < 8; kk++) {
            float a[8], b[8];
            *(float4*)&a[0] = *(const float4*)&As[kk][ty * 8];
            *(float4*)&a[4] = *(const float4*)&As[kk][ty * 8 + 4];
            *(float4*)&b[0] = *(const float4*)&Bs[kk][tx * 8];
            *(float4*)&b[4] = *(const float4*)&Bs[kk][tx * 8 + 4];
#pragma unroll
            for (int i = 0; i < 8; i++)
#pragma unroll
                for (int j = 0; j < 8; j++)
                    acc[i][j] = fmaf(a[i], b[j], acc[i][j]);
        }
        __syncthreads();
    }

#pragma unroll
    for (int i = 0; i < 8; i++) {
        float* cp = g_sim + (size_t)(m0 + ty * 8 + i) * B_SZ + n0 + tx * 8;
        *(float4*)cp       = make_float4(acc[i][0], acc[i][1], acc[i][2], acc[i][3]);
        *(float4*)(cp + 4) = make_float4(acc[i][4], acc[i][5], acc[i][6], acc[i][7]);
    }
}

// ---------------------------------------------------------------------------
// Bulk copy of the 8 state arrays input->output (scalar: out base misaligned
// for float4). blockIdx.y selects which array.
// ---------------------------------------------------------------------------
__global__ void copy8_kernel(const float* __restrict__ a0, const float* __restrict__ a1,
                             const float* __restrict__ a2, const float* __restrict__ a3,
                             const float* __restrict__ a4, const float* __restrict__ a5,
                             const float* __restrict__ a6, const float* __restrict__ a7,
                             float* __restrict__ dst, int n) {
    const float* srcs[8] = {a0, a1, a2, a3, a4, a5, a6, a7};
    const float* s = srcs[blockIdx.y];
    float* d = dst + (size_t)blockIdx.y * n;
    for (int i = blockIdx.x * blockDim.x + threadIdx.x; i < n;
         i += gridDim.x * blockDim.x)
        d[i] = s[i];
}

__device__ __forceinline__ float eta_from(const int* ep, const int* mep) {
    float f = (float)ep[0] / (float)mep[0];
    return ETA_MINV + (ETA_INIT - ETA_MINV) * cosf(1.57079632679f * f);
}

// ---------------------------------------------------------------------------
// Row (image) pass: one block per row i.
// ---------------------------------------------------------------------------
__global__ void row_kernel(const float* __restrict__ tau_I, const float* __restrict__ b_I,
                           const float* __restrict__ s_I, const float* __restrict__ u_I,
                           const int* __restrict__ image_ids,
                           const int* __restrict__ ep, const int* __restrict__ mep,
                           float* __restrict__ out, int N) {
    const int i = blockIdx.x;
    const int t = threadIdx.x;  // 256
    const float* row = g_sim + (size_t)i * B_SZ;
    const int id = image_ids[i];
    const float tau = tau_I[id];
    const float inv_tau = 1.0f / tau;
    const float diag = row[i];
    const float old_b = b_I[id];

    float m = -3.4e38f;
    for (int j = t; j < B_SZ; j += 256)
        m = fmaxf(m, (row[j] - diag) * inv_tau);
    m = warpMax(m);
    __shared__ float shm[8];
    __shared__ float bc;
    if ((t & 31) == 0) shm[t >> 5] = m;
    __syncthreads();
    if (t == 0) {
        float mm = shm[0];
#pragma unroll
        for (int w = 1; w < 8; w++) mm = fmaxf(mm, shm[w]);
        bc = fmaxf(mm, old_b);
    }
    __syncthreads();
    const float new_b = bc;

    float S = 0.f, E1 = 0.f, E2 = 0.f;
    for (int j = t; j < B_SZ; j += 256) {
        float d = row[j] - diag;
        float x = d * inv_tau;
        float e = __expf(x - new_b);
        S += e; E1 += e * d; E2 += e * x;
    }
    S = warpSum(S); E1 = warpSum(E1); E2 = warpSum(E2);
    __shared__ float shS[8], sh1[8], sh2[8];
    if ((t & 31) == 0) { shS[t >> 5] = S; sh1[t >> 5] = E1; sh2[t >> 5] = E2; }
    __syncthreads();
    if (t == 0) {
        float sS = 0, s1 = 0, s2 = 0;
#pragma unroll
        for (int w = 0; w < 8; w++) { sS += shS[w]; s1 += sh1[w]; s2 += sh2[w]; }
        const float rinv = 1.0f / (float)(B_SZ - 1);
        float gI = sS * rinv;
        float s_new = (1.0f - GAMMA_S) * s_I[id] * __expf(old_b - new_b) + GAMMA_S * gI;
        float denom = s_new + EPSV;
        float loss = s1 / denom * rinv;
        float grad = logf(s_new) + new_b + RHO - s2 / denom * rinv;
        float gcl = fminf(fmaxf(grad, -GRAD_CLIP), GRAD_CLIP);
        float u_new = (1.0f - GAMMA_U) * u_I[id] + GAMMA_U * gcl;
        float eta = eta_from(ep, mep);
        float tau_new = fminf(fmaxf(tau - eta * u_new, TAU_MINV), TAU_MAXV);

        out[i] = gI;                 // g_I
        out[2 * B_SZ + i] = grad;    // grad_tau_image
        g_loss_I[i] = loss;
        const size_t SB = 4 * B_SZ + 3;
        out[SB + (size_t)id] = s_new;                   // s_I_out
        out[SB + 2 * (size_t)N + id] = u_new;           // u_I_out
        out[SB + 4 * (size_t)N + id] = new_b;           // b_I_out
        out[SB + 6 * (size_t)N + id] = tau_new;         // tau_I_out
    }
}

// ---------------------------------------------------------------------------
// Column (text) pass: block covers 32 columns; (32,16) threads; global reads
// coalesced across tx.
// ---------------------------------------------------------------------------
__global__ void col_kernel(const float* __restrict__ tau_T, const float* __restrict__ b_T,
                           const float* __restrict__ s_T, const float* __restrict__ u_T,
                           const int* __restrict__ text_ids,
                           const int* __restrict__ ep, const int* __restrict__ mep,
                           float* __restrict__ out, int N) {
    const int tx = threadIdx.x;  // 0..31
    const int ty = threadIdx.y;  // 0..15
    const int j = blockIdx.x * 32 + tx;
    const int id = text_ids[j];
    const float tau = tau_T[id];
    const float inv_tau = 1.0f / tau;
    const float diag = g_sim[(size_t)j * B_SZ + j];
    const float old_b = b_T[id];

    __shared__ float rM[16][32];
    float m = -3.4e38f;
    for (int r = ty; r < B_SZ; r += 16)
        m = fmaxf(m, (g_sim[(size_t)r * B_SZ + j] - diag) * inv_tau);
    rM[ty][tx] = m;
    __syncthreads();
#pragma unroll
    for (int s = 8; s > 0; s >>= 1) {
        if (ty < s) rM[ty][tx] = fmaxf(rM[ty][tx], rM[ty + s][tx]);
        __syncthreads();
    }
    const float new_b = fmaxf(rM[0][tx], old_b);
    __syncthreads();

    float S = 0.f, E1 = 0.f, E2 = 0.f;
    for (int r = ty; r < B_SZ; r += 16) {
        float d = g_sim[(size_t)r * B_SZ + j] - diag;
        float x = d * inv_tau;
        float e = __expf(x - new_b);
        S += e; E1 += e * d; E2 += e * x;
    }
    __shared__ float rS[16][32], r1[16][32], r2[16][32];
    rS[ty][tx] = S; r1[ty][tx] = E1; r2[ty][tx] = E2;
    __syncthreads();
#pragma unroll
    for (int s = 8; s > 0; s >>= 1) {
        if (ty < s) {
            rS[ty][tx] += rS[ty + s][tx];
            r1[ty][tx] += r1[ty + s][tx];
            r2[ty][tx] += r2[ty + s][tx];
        }
        __syncthreads();
    }
    if (ty == 0) {
        float sS = rS[0][tx], s1 = r1[0][tx], s2 = r2[0][tx];
        const float rinv = 1.0f / (float)(B_SZ - 1);
        float gT = sS * rinv;
        float s_new = (1.0f - GAMMA_S) * s_T[id] * __expf(old_b - new_b) + GAMMA_S * gT;
        float denom = s_new + EPSV;
        float loss = s1 / denom * rinv;
        float grad = logf(s_new) + new_b + RHO - s2 / denom * rinv;
        float gcl = fminf(fmaxf(grad, -GRAD_CLIP), GRAD_CLIP);
        float u_new = (1.0f - GAMMA_U) * u_T[id] + GAMMA_U * gcl;
        float eta = eta_from(ep, mep);
        float tau_new = fminf(fmaxf(tau - eta * u_new, TAU_MINV), TAU_MAXV);

        out[B_SZ + j] = gT;              // g_T
        out[3 * B_SZ + j] = grad;        // grad_tau_text
        g_loss_T[j] = loss;
        const size_t SB = 4 * B_SZ + 3;
        out[SB + (size_t)N + id] = s_new;               // s_T_out
        out[SB + 3 * (size_t)N + id] = u_new;           // u_T_out
        out[SB + 5 * (size_t)N + id] = new_b;           // b_T_out
        out[SB + 7 * (size_t)N + id] = tau_new;         // tau_T_out
    }
}

// ---------------------------------------------------------------------------
// Deterministic scalar finalize: total_loss + avg taus.
// ---------------------------------------------------------------------------
__global__ void finalize_kernel(const float* __restrict__ tau_I, const float* __restrict__ tau_T,
                                const int* __restrict__ iid, const int* __restrict__ tid_,
                                float* __restrict__ out) {
    const int t = threadIdx.x;  // 1024
    float lI = 0, lT = 0, tI = 0, tT = 0;
    for (int i = t; i < B_SZ; i += 1024) {
        lI += g_loss_I[i];
        lT += g_loss_T[i];
        tI += tau_I[iid[i]];
        tT += tau_T[tid_[i]];
    }
    lI = warpSum(lI); lT = warpSum(lT); tI = warpSum(tI); tT = warpSum(tT);
    __shared__ float sh[32][4];
    if ((t & 31) == 0) {
        int w = t >> 5;
        sh[w][0] = lI; sh[w][1] = lT; sh[w][2] = tI; sh[w][3] = tT;
    }
    __syncthreads();
    if (t == 0) {
        float a = 0, b = 0, c = 0, d = 0;
        for (int w = 0; w < 32; w++) { a += sh[w][0]; b += sh[w][1]; c += sh[w][2]; d += sh[w][3]; }
        const float invB = 1.0f / (float)B_SZ;
        out[4 * B_SZ + 0] = a * invB + b * invB;  // total_loss
        out[4 * B_SZ + 1] = c * invB;             // avg_image_tau
        out[4 * B_SZ + 2] = d * invB;             // avg_text_tau
    }
}

extern "C" void kernel_launch(void* const* d_in, const int* in_sizes, int n_in,
                              void* d_out, int out_size) {
    const float* imf   = (const float*)d_in[0];
    const float* txf   = (const float*)d_in[1];
    const float* s_I   = (const float*)d_in[2];
    const float* s_T   = (const float*)d_in[3];
    const float* tau_I = (const float*)d_in[4];
    const float* tau_T = (const float*)d_in[5];
    const float* u_I   = (const float*)d_in[6];
    const float* u_T   = (const float*)d_in[7];
    const float* b_I   = (const float*)d_in[8];
    const float* b_T   = (const float*)d_in[9];
    const int* iid     = (const int*)d_in[10];
    const int* tid     = (const int*)d_in[11];
    const int* ep      = (const int*)d_in[12];
    const int* mep     = (const int*)d_in[13];
    float* out = (float*)d_out;
    const int N = in_sizes[2];  // 2,900,000

    // 1) similarity GEMM -> g_sim
    gemm_kernel<<<dim3(B_SZ / 128, B_SZ / 128), 256>>>(imf, txf);

    // 2) bulk copy state arrays to output (order: s_I, s_T, u_I, u_T, b_I, b_T, tau_I, tau_T)
    copy8_kernel<<<dim3(1024, 8), 256>>>(s_I, s_T, u_I, u_T, b_I, b_T, tau_I, tau_T,
                                         out + 4 * B_SZ + 3, N);

    // 3) row (image) pass: g_I, grad_tau_image, scatter updates
    row_kernel<<<B_SZ, 256>>>(tau_I, b_I, s_I, u_I, iid, ep, mep, out, N);

    // 4) column (text) pass: g_T, grad_tau_text, scatter updates
    col_kernel<<<B_SZ / 32, dim3(32, 16)>>>(tau_T, b_T, s_T, u_T, tid, ep, mep, out, N);

    // 5) scalars
    finalize_kernel<<<1, 1024>>>(tau_I, tau_T, iid, tid, out);
}

// round 6
// speedup vs baseline: 1.1643x; 1.1643x over previous
#include <cuda_runtime.h>
#include <math.h>
#include <stdint.h>
#include <float.h>

#define B_SZ 4096
#define DIM  1024
#define GAMMA_S 0.8f
#define GAMMA_U 0.8f
#define RHO     0.1f
#define EPSV    1e-10f
#define TAU_MINV 0.005f
#define TAU_MAXV 1.0f
#define GRAD_CLIP 5.0f
#define ETA_INIT 0.01f
#define ETA_MINV 0.0001f

// 64MB scratch for the similarity matrix + per-row/col loss scratch.
__device__ float g_sim[B_SZ * B_SZ];
__device__ float g_loss_I[B_SZ];
__device__ float g_loss_T[B_SZ];

__device__ __forceinline__ float warpMax(float v) {
#pragma unroll
    for (int o = 16; o > 0; o >>= 1) v = fmaxf(v, __shfl_xor_sync(0xffffffffu, v, o));
    return v;
}
__device__ __forceinline__ float warpSum(float v) {
#pragma unroll
    for (int o = 16; o > 0; o >>= 1) v += __shfl_xor_sync(0xffffffffu, v, o);
    return v;
}

// ---------------------------------------------------------------------------
// 3xTF32 tensor-core GEMM: g_sim[i][j] = sum_d A[i][d] * B[j][d]
// CTA 128x128, BK=16, 256 threads (8 warps, each 64x32), mma.m16n8k8.tf32.
// Each fp32 value is split hi+lo (both tf32); 3 mma passes recover ~fp32.
// ---------------------------------------------------------------------------
__device__ __forceinline__ uint32_t f2tf32(float v) {
    uint32_t r;
    asm("cvt.rna.tf32.f32 %0, %1;" : "=r"(r) : "f"(v));
    return r;
}

__device__ __forceinline__ void mma8(float* c, const uint32_t* a, const uint32_t* b) {
    asm volatile(
        "mma.sync.aligned.m16n8k8.row.col.f32.tf32.tf32.f32 "
        "{%0,%1,%2,%3},{%4,%5,%6,%7},{%8,%9},{%0,%1,%2,%3};\n"
        : "+f"(c[0]), "+f"(c[1]), "+f"(c[2]), "+f"(c[3])
        : "r"(a[0]), "r"(a[1]), "r"(a[2]), "r"(a[3]), "r"(b[0]), "r"(b[1]));
}

#define BK 16
#define LDSS 20   // smem row stride (pad 4) -> conflict-free frag loads

__global__ __launch_bounds__(256) void gemm_tf32(const float* __restrict__ A,
                                                 const float* __restrict__ Bm) {
    __shared__ uint32_t Ah[128][LDSS], Al[128][LDSS];
    __shared__ uint32_t Bh[128][LDSS], Bl[128][LDSS];

    const int t = threadIdx.x;
    const int m0 = blockIdx.y * 128, n0 = blockIdx.x * 128;
    const int wid = t >> 5, lane = t & 31;
    const int wm = (wid & 1) * 64;      // warp row base (2 warps over M)
    const int wn = (wid >> 1) * 32;     // warp col base (4 warps over N)
    const int gp = lane >> 2;           // 0..7
    const int tg = lane & 3;            // 0..3

    float c[4][4][4];
#pragma unroll
    for (int mt = 0; mt < 4; mt++)
#pragma unroll
        for (int nt = 0; nt < 4; nt++)
#pragma unroll
            for (int q = 0; q < 4; q++) c[mt][nt][q] = 0.0f;

    // global load mapping: thread loads 2 float4 from each of A,B per chunk
    const int r0 = t >> 2;              // 0..63
    const int kc0 = (t & 3) << 2;       // 0,4,8,12
    const float* Ap = A  + (size_t)(m0 + r0) * DIM + kc0;
    const float* Bp = Bm + (size_t)(n0 + r0) * DIM + kc0;

    float4 pa0 = *(const float4*)(Ap);
    float4 pa1 = *(const float4*)(Ap + 64 * DIM);
    float4 pb0 = *(const float4*)(Bp);
    float4 pb1 = *(const float4*)(Bp + 64 * DIM);

    for (int kc = 0; kc < DIM / BK; kc++) {
        __syncthreads();  // previous compute done; smem safe to overwrite
        {
            float va[8] = {pa0.x, pa0.y, pa0.z, pa0.w, pa1.x, pa1.y, pa1.z, pa1.w};
            float vb[8] = {pb0.x, pb0.y, pb0.z, pb0.w, pb1.x, pb1.y, pb1.z, pb1.w};
#pragma unroll
            for (int q = 0; q < 4; q++) {
                uint32_t h;
                h = f2tf32(va[q]);
                Ah[r0][kc0 + q] = h; Al[r0][kc0 + q] = f2tf32(va[q] - __uint_as_float(h));
                h = f2tf32(va[4 + q]);
                Ah[r0 + 64][kc0 + q] = h; Al[r0 + 64][kc0 + q] = f2tf32(va[4 + q] - __uint_as_float(h));
                h = f2tf32(vb[q]);
                Bh[r0][kc0 + q] = h; Bl[r0][kc0 + q] = f2tf32(vb[q] - __uint_as_float(h));
                h = f2tf32(vb[4 + q]);
                Bh[r0 + 64][kc0 + q] = h; Bl[r0 + 64][kc0 + q] = f2tf32(vb[4 + q] - __uint_as_float(h));
            }
        }
        if (kc + 1 < DIM / BK) {
            int ko = (kc + 1) * BK;
            pa0 = *(const float4*)(Ap + ko);
            pa1 = *(const float4*)(Ap + ko + 64 * DIM);
            pb0 = *(const float4*)(Bp + ko);
            pb1 = *(const float4*)(Bp + ko + 64 * DIM);
        }
        __syncthreads();

#pragma unroll
        for (int ks = 0; ks < 2; ks++) {
            const int kb = ks * 8 + tg;
            uint32_t ah[4][4], al[4][4], bh[4][2], bl[4][2];
#pragma unroll
            for (int mt = 0; mt < 4; mt++) {
                const int rr = wm + mt * 16 + gp;
                ah[mt][0] = Ah[rr][kb];     ah[mt][1] = Ah[rr + 8][kb];
                ah[mt][2] = Ah[rr][kb + 4]; ah[mt][3] = Ah[rr + 8][kb + 4];
                al[mt][0] = Al[rr][kb];     al[mt][1] = Al[rr + 8][kb];
                al[mt][2] = Al[rr][kb + 4]; al[mt][3] = Al[rr + 8][kb + 4];
            }
#pragma unroll
            for (int nt = 0; nt < 4; nt++) {
                const int cc = wn + nt * 8 + gp;
                bh[nt][0] = Bh[cc][kb]; bh[nt][1] = Bh[cc][kb + 4];
                bl[nt][0] = Bl[cc][kb]; bl[nt][1] = Bl[cc][kb + 4];
            }
#pragma unroll
            for (int mt = 0; mt < 4; mt++)
#pragma unroll
                for (int nt = 0; nt < 4; nt++) {
                    mma8(c[mt][nt], ah[mt], bh[nt]);
                    mma8(c[mt][nt], ah[mt], bl[nt]);
                    mma8(c[mt][nt], al[mt], bh[nt]);
                }
        }
    }

    // epilogue: c layout m16n8 -> (row = gp / gp+8, col = tg*2 / tg*2+1)
#pragma unroll
    for (int mt = 0; mt < 4; mt++) {
        const int rr = m0 + wm + mt * 16 + gp;
#pragma unroll
        for (int nt = 0; nt < 4; nt++) {
            const int cc = n0 + wn + nt * 8 + tg * 2;
            *(float2*)(g_sim + (size_t)rr * B_SZ + cc) =
                make_float2(c[mt][nt][0], c[mt][nt][1]);
            *(float2*)(g_sim + (size_t)(rr + 8) * B_SZ + cc) =
                make_float2(c[mt][nt][2], c[mt][nt][3]);
        }
    }
}

// ---------------------------------------------------------------------------
// Bulk copy of the 8 state arrays input->output.
// ---------------------------------------------------------------------------
__global__ void copy8_kernel(const float* __restrict__ a0, const float* __restrict__ a1,
                             const float* __restrict__ a2, const float* __restrict__ a3,
                             const float* __restrict__ a4, const float* __restrict__ a5,
                             const float* __restrict__ a6, const float* __restrict__ a7,
                             float* __restrict__ dst, int n) {
    const float* srcs[8] = {a0, a1, a2, a3, a4, a5, a6, a7};
    const float* s = srcs[blockIdx.y];
    float* d = dst + (size_t)blockIdx.y * n;
    for (int i = blockIdx.x * blockDim.x + threadIdx.x; i < n;
         i += gridDim.x * blockDim.x)
        d[i] = s[i];
}

__device__ __forceinline__ float eta_from(const int* ep, const int* mep) {
    float f = (float)ep[0] / (float)mep[0];
    return ETA_MINV + (ETA_INIT - ETA_MINV) * cosf(1.57079632679f * f);
}

// ---------------------------------------------------------------------------
// Row (image) pass: one block per row; row cached in smem (single DRAM read).
// ---------------------------------------------------------------------------
__global__ __launch_bounds__(256) void row_kernel(
        const float* __restrict__ tau_I, const float* __restrict__ b_I,
        const float* __restrict__ s_I, const float* __restrict__ u_I,
        const int* __restrict__ image_ids,
        const int* __restrict__ ep, const int* __restrict__ mep,
        float* __restrict__ out, int N) {
    __shared__ float buf[B_SZ];
    const int i = blockIdx.x;
    const int t = threadIdx.x;  // 256
    const float* row = g_sim + (size_t)i * B_SZ;
    const int id = image_ids[i];
    const float tau = tau_I[id];
    const float inv_tau = 1.0f / tau;
    const float diag = row[i];
    const float old_b = b_I[id];

    // pass 1: load row -> smem, track raw max (inv_tau > 0 so max commutes)
    float mv = -FLT_MAX;
#pragma unroll
    for (int q = 0; q < 4; q++) {
        int j4 = (t + q * 256) * 4;
        float4 v = *(const float4*)(row + j4);
        *(float4*)(buf + j4) = v;
        mv = fmaxf(mv, fmaxf(fmaxf(v.x, v.y), fmaxf(v.z, v.w)));
    }
    mv = warpMax(mv);
    __shared__ float shm[8];
    __shared__ float bc;
    if ((t & 31) == 0) shm[t >> 5] = mv;
    __syncthreads();
    if (t == 0) {
        float mm = shm[0];
#pragma unroll
        for (int w = 1; w < 8; w++) mm = fmaxf(mm, shm[w]);
        bc = fmaxf((mm - diag) * inv_tau, old_b);
    }
    __syncthreads();
    const float new_b = bc;

    float S = 0.f, E1 = 0.f, E2 = 0.f;
    for (int j = t; j < B_SZ; j += 256) {
        float d = buf[j] - diag;
        float x = d * inv_tau;
        float e = __expf(x - new_b);
        S += e; E1 += e * d; E2 += e * x;
    }
    S = warpSum(S); E1 = warpSum(E1); E2 = warpSum(E2);
    __shared__ float shS[8], sh1[8], sh2[8];
    if ((t & 31) == 0) { shS[t >> 5] = S; sh1[t >> 5] = E1; sh2[t >> 5] = E2; }
    __syncthreads();
    if (t == 0) {
        float sS = 0, s1 = 0, s2 = 0;
#pragma unroll
        for (int w = 0; w < 8; w++) { sS += shS[w]; s1 += sh1[w]; s2 += sh2[w]; }
        const float rinv = 1.0f / (float)(B_SZ - 1);
        float gI = sS * rinv;
        float s_new = (1.0f - GAMMA_S) * s_I[id] * __expf(old_b - new_b) + GAMMA_S * gI;
        float denom = s_new + EPSV;
        float loss = s1 / denom * rinv;
        float grad = logf(s_new) + new_b + RHO - s2 / denom * rinv;
        float gcl = fminf(fmaxf(grad, -GRAD_CLIP), GRAD_CLIP);
        float u_new = (1.0f - GAMMA_U) * u_I[id] + GAMMA_U * gcl;
        float eta = eta_from(ep, mep);
        float tau_new = fminf(fmaxf(tau - eta * u_new, TAU_MINV), TAU_MAXV);

        out[i] = gI;                 // g_I
        out[2 * B_SZ + i] = grad;    // grad_tau_image
        g_loss_I[i] = loss;
        const size_t SB = 4 * B_SZ + 3;
        out[SB + (size_t)id] = s_new;           // s_I_out
        out[SB + 2 * (size_t)N + id] = u_new;   // u_I_out
        out[SB + 4 * (size_t)N + id] = new_b;   // b_I_out
        out[SB + 6 * (size_t)N + id] = tau_new; // tau_I_out
    }
}

// ---------------------------------------------------------------------------
// Column (text) pass: single-pass online max/sum. Block (32,32), 32 columns.
// ---------------------------------------------------------------------------
__global__ __launch_bounds__(1024) void col_kernel(
        const float* __restrict__ tau_T, const float* __restrict__ b_T,
        const float* __restrict__ s_T, const float* __restrict__ u_T,
        const int* __restrict__ text_ids,
        const int* __restrict__ ep, const int* __restrict__ mep,
        float* __restrict__ out, int N) {
    const int tx = threadIdx.x;  // 0..31 -> column lane
    const int ty = threadIdx.y;  // 0..31 -> row stripe
    const int j = blockIdx.x * 32 + tx;
    const int id = text_ids[j];
    const float tau = tau_T[id];
    const float inv_tau = 1.0f / tau;
    const float diag = g_sim[(size_t)j * B_SZ + j];
    const float old_b = b_T[id];

    // online accumulation over this thread's 128 rows
    float m = -FLT_MAX, S = 0.f, E1 = 0.f, E2 = 0.f;
    for (int r = ty; r < B_SZ; r += 32) {
        float d = g_sim[(size_t)r * B_SZ + j] - diag;
        float x = d * inv_tau;
        if (x > m) {
            float sc = __expf(m - x);   // exp(-inf)=0 handles first iter
            S = S * sc + 1.0f;
            E1 = E1 * sc + d;
            E2 = E2 * sc + x;
            m = x;
        } else {
            float e = __expf(x - m);
            S += e; E1 += e * d; E2 += e * x;
        }
    }

    __shared__ float sm[32][33], sS[32][33], s1m[32][33], s2m[32][33];
    sm[ty][tx] = m; sS[ty][tx] = S; s1m[ty][tx] = E1; s2m[ty][tx] = E2;
    __syncthreads();

    if (ty == 0) {
        float M = -FLT_MAX;
#pragma unroll
        for (int k = 0; k < 32; k++) M = fmaxf(M, sm[k][tx]);
        const float new_b = fmaxf(M, old_b);
        float Ss = 0.f, e1 = 0.f, e2 = 0.f;
#pragma unroll
        for (int k = 0; k < 32; k++) {
            float sc = __expf(sm[k][tx] - new_b);
            Ss += sS[k][tx] * sc;
            e1 += s1m[k][tx] * sc;
            e2 += s2m[k][tx] * sc;
        }
        const float rinv = 1.0f / (float)(B_SZ - 1);
        float gT = Ss * rinv;
        float s_new = (1.0f - GAMMA_S) * s_T[id] * __expf(old_b - new_b) + GAMMA_S * gT;
        float denom = s_new + EPSV;
        float loss = e1 / denom * rinv;
        float grad = logf(s_new) + new_b + RHO - e2 / denom * rinv;
        float gcl = fminf(fmaxf(grad, -GRAD_CLIP), GRAD_CLIP);
        float u_new = (1.0f - GAMMA_U) * u_T[id] + GAMMA_U * gcl;
        float eta = eta_from(ep, mep);
        float tau_new = fminf(fmaxf(tau - eta * u_new, TAU_MINV), TAU_MAXV);

        out[B_SZ + j] = gT;              // g_T
        out[3 * B_SZ + j] = grad;        // grad_tau_text
        g_loss_T[j] = loss;
        const size_t SB = 4 * B_SZ + 3;
        out[SB + (size_t)N + id] = s_new;           // s_T_out
        out[SB + 3 * (size_t)N + id] = u_new;       // u_T_out
        out[SB + 5 * (size_t)N + id] = new_b;       // b_T_out
        out[SB + 7 * (size_t)N + id] = tau_new;     // tau_T_out
    }
}

// ---------------------------------------------------------------------------
// Deterministic scalar finalize: total_loss + avg taus.
// ---------------------------------------------------------------------------
__global__ void finalize_kernel(const float* __restrict__ tau_I, const float* __restrict__ tau_T,
                                const int* __restrict__ iid, const int* __restrict__ tid_,
                                float* __restrict__ out) {
    const int t = threadIdx.x;  // 1024
    float lI = 0, lT = 0, tI = 0, tT = 0;
    for (int i = t; i < B_SZ; i += 1024) {
        lI += g_loss_I[i];
        lT += g_loss_T[i];
        tI += tau_I[iid[i]];
        tT += tau_T[tid_[i]];
    }
    lI = warpSum(lI); lT = warpSum(lT); tI = warpSum(tI); tT = warpSum(tT);
    __shared__ float sh[32][4];
    if ((t & 31) == 0) {
        int w = t >> 5;
        sh[w][0] = lI; sh[w][1] = lT; sh[w][2] = tI; sh[w][3] = tT;
    }
    __syncthreads();
    if (t == 0) {
        float a = 0, b = 0, c = 0, d = 0;
        for (int w = 0; w < 32; w++) { a += sh[w][0]; b += sh[w][1]; c += sh[w][2]; d += sh[w][3]; }
        const float invB = 1.0f / (float)B_SZ;
        out[4 * B_SZ + 0] = a * invB + b * invB;  // total_loss
        out[4 * B_SZ + 1] = c * invB;             // avg_image_tau
        out[4 * B_SZ + 2] = d * invB;             // avg_text_tau
    }
}

extern "C" void kernel_launch(void* const* d_in, const int* in_sizes, int n_in,
                              void* d_out, int out_size) {
    const float* imf   = (const float*)d_in[0];
    const float* txf   = (const float*)d_in[1];
    const float* s_I   = (const float*)d_in[2];
    const float* s_T   = (const float*)d_in[3];
    const float* tau_I = (const float*)d_in[4];
    const float* tau_T = (const float*)d_in[5];
    const float* u_I   = (const float*)d_in[6];
    const float* u_T   = (const float*)d_in[7];
    const float* b_I   = (const float*)d_in[8];
    const float* b_T   = (const float*)d_in[9];
    const int* iid     = (const int*)d_in[10];
    const int* tid     = (const int*)d_in[11];
    const int* ep      = (const int*)d_in[12];
    const int* mep     = (const int*)d_in[13];
    float* out = (float*)d_out;
    const int N = in_sizes[2];  // 2,900,000

    // 1) similarity GEMM (3xTF32 tensor cores) -> g_sim
    gemm_tf32<<<dim3(B_SZ / 128, B_SZ / 128), 256>>>(imf, txf);

    // 2) bulk copy state arrays to output (s_I, s_T, u_I, u_T, b_I, b_T, tau_I, tau_T)
    copy8_kernel<<<dim3(1024, 8), 256>>>(s_I, s_T, u_I, u_T, b_I, b_T, tau_I, tau_T,
                                         out + 4 * B_SZ + 3, N);

    // 3) row (image) pass
    row_kernel<<<B_SZ, 256>>>(tau_I, b_I, s_I, u_I, iid, ep, mep, out, N);

    // 4) column (text) pass
    col_kernel<<<B_SZ / 32, dim3(32, 32)>>>(tau_T, b_T, s_T, u_T, tid, ep, mep, out, N);

    // 5) scalars
    finalize_kernel<<<1, 1024>>>(tau_I, tau_T, iid, tid, out);
}

// round 11
// speedup vs baseline: 2.1137x; 1.8155x over previous
#include <cuda_runtime.h>
#include <cuda_fp16.h>
#include <math.h>
#include <stdint.h>
#include <float.h>

#define B_SZ 4096
#define DIM  1024
#define GAMMA_S 0.8f
#define GAMMA_U 0.8f
#define RHO     0.1f
#define EPSV    1e-10f
#define TAU_MINV 0.005f
#define TAU_MAXV 1.0f
#define GRAD_CLIP 5.0f
#define ETA_INIT 0.01f
#define ETA_MINV 0.0001f

// Scratch: sim matrix (64MB) + fp16 split operands (32MB) + loss vectors.
__device__ float g_sim[B_SZ * B_SZ];
__device__ float g_loss_I[B_SZ];
__device__ float g_loss_T[B_SZ];
__device__ __half g_Ahi[B_SZ * DIM];
__device__ __half g_Alo[B_SZ * DIM];
__device__ __half g_Bhi[B_SZ * DIM];
__device__ __half g_Blo[B_SZ * DIM];

__device__ __forceinline__ float warpMax(float v) {
#pragma unroll
    for (int o = 16; o > 0; o >>= 1) v = fmaxf(v, __shfl_xor_sync(0xffffffffu, v, o));
    return v;
}
__device__ __forceinline__ float warpSum(float v) {
#pragma unroll
    for (int o = 16; o > 0; o >>= 1) v += __shfl_xor_sync(0xffffffffu, v, o);
    return v;
}

// ───────────────────── split-fp16 convert pre-pass ─────────────────────
__global__ __launch_bounds__(256) void convert_kernel(const float* __restrict__ imf,
                                                      const float* __restrict__ txf) {
    const int n4 = B_SZ * DIM / 4;
    for (int i = blockIdx.x * blockDim.x + threadIdx.x; i < n4;
         i += gridDim.x * blockDim.x) {
        float4 a = ((const float4*)imf)[i];
        float4 b = ((const float4*)txf)[i];
        float av[4] = {a.x, a.y, a.z, a.w};
        float bv[4] = {b.x, b.y, b.z, b.w};
        __half2* ah = (__half2*)g_Ahi + i * 2;
        __half2* al = (__half2*)g_Alo + i * 2;
        __half2* bh = (__half2*)g_Bhi + i * 2;
        __half2* bl = (__half2*)g_Blo + i * 2;
        __half hi[4], lo[4], hib[4], lob[4];
#pragma unroll
        for (int q = 0; q < 4; q++) {
            hi[q]  = __float2half_rn(av[q]);
            lo[q]  = __float2half_rn(av[q] - __half2float(hi[q]));
            hib[q] = __float2half_rn(bv[q]);
            lob[q] = __float2half_rn(bv[q] - __half2float(hib[q]));
        }
        ah[0] = __halves2half2(hi[0], hi[1]);   ah[1] = __halves2half2(hi[2], hi[3]);
        al[0] = __halves2half2(lo[0], lo[1]);   al[1] = __halves2half2(lo[2], lo[3]);
        bh[0] = __halves2half2(hib[0], hib[1]); bh[1] = __halves2half2(hib[2], hib[3]);
        bl[0] = __halves2half2(lob[0], lob[1]); bl[1] = __halves2half2(lob[2], lob[3]);
    }
}

// ───────────────── 3xFP16 mma.sync GEMM: g_sim = A·Bᵀ ─────────────────
// CTA 128x128, BK=32 halves, 256 threads (8 warps: 2 over M x 4 over N,
// warp tile 64x32), mma.m16n8k16.f16 with fp32 accum, hi/lo 3-product split.
__device__ __forceinline__ void mma16(float* c, const uint32_t* a, const uint32_t* b) {
    asm volatile(
        "mma.sync.aligned.m16n8k16.row.col.f32.f16.f16.f32 "
        "{%0,%1,%2,%3},{%4,%5,%6,%7},{%8,%9},{%0,%1,%2,%3};\n"
        : "+f"(c[0]), "+f"(c[1]), "+f"(c[2]), "+f"(c[3])
        : "r"(a[0]), "r"(a[1]), "r"(a[2]), "r"(a[3]), "r"(b[0]), "r"(b[1]));
}

#define BKH 32                 // k halves per chunk
#define NCH (DIM / BKH)        // 32 chunks
#define LDH 40                 // padded smem row stride (halves)

__global__ __launch_bounds__(256) void gemm_fp16(void) {
    __shared__ __half Ahs[128 * LDH], Als[128 * LDH];
    __shared__ __half Bhs[128 * LDH], Bls[128 * LDH];

    const int t = threadIdx.x;
    const int m0 = blockIdx.y * 128, n0 = blockIdx.x * 128;
    const int wid = t >> 5, lane = t & 31;
    const int wm = (wid & 1) * 64;     // warp row base
    const int wn = (wid >> 1) * 32;    // warp col base
    const int gp = lane >> 2;          // 0..7
    const int tg = lane & 3;           // 0..3

    float c[4][4][4];
#pragma unroll
    for (int mt = 0; mt < 4; mt++)
#pragma unroll
        for (int nt = 0; nt < 4; nt++)
#pragma unroll
            for (int q = 0; q < 4; q++) c[mt][nt][q] = 0.0f;

    // gmem load mapping: tile = 128 rows x 4 uint4 (32 halves); 2 vec/thread/tile
    const int r0 = t >> 2;             // row (0..63), second row = r0+64
    const int c0 = t & 3;              // uint4 column (0..3)

    const __half* gAh = g_Ahi + (size_t)(m0 + r0) * DIM + c0 * 8;
    const __half* gAl = g_Alo + (size_t)(m0 + r0) * DIM + c0 * 8;
    const __half* gBh = g_Bhi + (size_t)(n0 + r0) * DIM + c0 * 8;
    const __half* gBl = g_Blo + (size_t)(n0 + r0) * DIM + c0 * 8;
    const size_t half64 = (size_t)64 * DIM;

    uint4 pah0 = *(const uint4*)(gAh);
    uint4 pah1 = *(const uint4*)(gAh + half64);
    uint4 pal0 = *(const uint4*)(gAl);
    uint4 pal1 = *(const uint4*)(gAl + half64);
    uint4 pbh0 = *(const uint4*)(gBh);
    uint4 pbh1 = *(const uint4*)(gBh + half64);
    uint4 pbl0 = *(const uint4*)(gBl);
    uint4 pbl1 = *(const uint4*)(gBl + half64);

    for (int kc = 0; kc < NCH; kc++) {
        __syncthreads();  // previous compute done
        {
            uint4* dA0 = (uint4*)(Ahs + r0 * LDH + c0 * 8);
            uint4* dA1 = (uint4*)(Ahs + (r0 + 64) * LDH + c0 * 8);
            uint4* eA0 = (uint4*)(Als + r0 * LDH + c0 * 8);
            uint4* eA1 = (uint4*)(Als + (r0 + 64) * LDH + c0 * 8);
            uint4* dB0 = (uint4*)(Bhs + r0 * LDH + c0 * 8);
            uint4* dB1 = (uint4*)(Bhs + (r0 + 64) * LDH + c0 * 8);
            uint4* eB0 = (uint4*)(Bls + r0 * LDH + c0 * 8);
            uint4* eB1 = (uint4*)(Bls + (r0 + 64) * LDH + c0 * 8);
            *dA0 = pah0; *dA1 = pah1; *eA0 = pal0; *eA1 = pal1;
            *dB0 = pbh0; *dB1 = pbh1; *eB0 = pbl0; *eB1 = pbl1;
        }
        if (kc + 1 < NCH) {
            const int ko = (kc + 1) * BKH;
            pah0 = *(const uint4*)(gAh + ko);
            pah1 = *(const uint4*)(gAh + ko + half64);
            pal0 = *(const uint4*)(gAl + ko);
            pal1 = *(const uint4*)(gAl + ko + half64);
            pbh0 = *(const uint4*)(gBh + ko);
            pbh1 = *(const uint4*)(gBh + ko + half64);
            pbl0 = *(const uint4*)(gBl + ko);
            pbl1 = *(const uint4*)(gBl + ko + half64);
        }
        __syncthreads();

#pragma unroll
        for (int ks = 0; ks < 2; ks++) {
            const int kb  = ks * 16 + 2 * tg;  // lower k-pair
            const int kb8 = kb + 8;            // upper k-pair
            uint32_t ah[4][4], al[4][4], bh[4][2], bl[4][2];
#pragma unroll
            for (int mt = 0; mt < 4; mt++) {
                const __half* arh = Ahs + (wm + mt * 16 + gp) * LDH;
                const __half* arl = Als + (wm + mt * 16 + gp) * LDH;
                ah[mt][0] = *(const uint32_t*)(arh + kb);
                ah[mt][1] = *(const uint32_t*)(arh + 8 * LDH + kb);
                ah[mt][2] = *(const uint32_t*)(arh + kb8);
                ah[mt][3] = *(const uint32_t*)(arh + 8 * LDH + kb8);
                al[mt][0] = *(const uint32_t*)(arl + kb);
                al[mt][1] = *(const uint32_t*)(arl + 8 * LDH + kb);
                al[mt][2] = *(const uint32_t*)(arl + kb8);
                al[mt][3] = *(const uint32_t*)(arl + 8 * LDH + kb8);
            }
#pragma unroll
            for (int nt = 0; nt < 4; nt++) {
                const __half* brh = Bhs + (wn + nt * 8 + gp) * LDH;
                const __half* brl = Bls + (wn + nt * 8 + gp) * LDH;
                bh[nt][0] = *(const uint32_t*)(brh + kb);
                bh[nt][1] = *(const uint32_t*)(brh + kb8);
                bl[nt][0] = *(const uint32_t*)(brl + kb);
                bl[nt][1] = *(const uint32_t*)(brl + kb8);
            }
#pragma unroll
            for (int mt = 0; mt < 4; mt++)
#pragma unroll
                for (int nt = 0; nt < 4; nt++) {
                    mma16(c[mt][nt], ah[mt], bh[nt]);
                    mma16(c[mt][nt], ah[mt], bl[nt]);
                    mma16(c[mt][nt], al[mt], bh[nt]);
                }
        }
    }

    // epilogue: c layout m16n8 -> rows gp/gp+8, cols 2*tg..+1
#pragma unroll
    for (int mt = 0; mt < 4; mt++) {
        const int rr = m0 + wm + mt * 16 + gp;
#pragma unroll
        for (int nt = 0; nt < 4; nt++) {
            const int cc = n0 + wn + nt * 8 + tg * 2;
            *(float2*)(g_sim + (size_t)rr * B_SZ + cc) =
                make_float2(c[mt][nt][0], c[mt][nt][1]);
            *(float2*)(g_sim + (size_t)(rr + 8) * B_SZ + cc) =
                make_float2(c[mt][nt][2], c[mt][nt][3]);
        }
    }
}

// ───────────────────── elementwise / reduction kernels ─────────────────────
__global__ void copy8_kernel(const float* __restrict__ a0, const float* __restrict__ a1,
                             const float* __restrict__ a2, const float* __restrict__ a3,
                             const float* __restrict__ a4, const float* __restrict__ a5,
                             const float* __restrict__ a6, const float* __restrict__ a7,
                             float* __restrict__ dst, int n) {
    const float* srcs[8] = {a0, a1, a2, a3, a4, a5, a6, a7};
    const float* s = srcs[blockIdx.y];
    float* d = dst + (size_t)blockIdx.y * n;
    for (int i = blockIdx.x * blockDim.x + threadIdx.x; i < n;
         i += gridDim.x * blockDim.x)
        d[i] = s[i];
}

__device__ __forceinline__ float eta_from(const int* ep, const int* mep) {
    float f = (float)ep[0] / (float)mep[0];
    return ETA_MINV + (ETA_INIT - ETA_MINV) * cosf(1.57079632679f * f);
}

__global__ __launch_bounds__(256) void row_kernel(
        const float* __restrict__ tau_I, const float* __restrict__ b_I,
        const float* __restrict__ s_I, const float* __restrict__ u_I,
        const int* __restrict__ image_ids,
        const int* __restrict__ ep, const int* __restrict__ mep,
        float* __restrict__ out, int N) {
    __shared__ float buf[B_SZ];
    const int i = blockIdx.x;
    const int t = threadIdx.x;  // 256
    const float* row = g_sim + (size_t)i * B_SZ;
    const int id = image_ids[i];
    const float tau = tau_I[id];
    const float inv_tau = 1.0f / tau;
    const float diag = row[i];
    const float old_b = b_I[id];

    float mv = -FLT_MAX;
#pragma unroll
    for (int q = 0; q < 4; q++) {
        int j4 = (t + q * 256) * 4;
        float4 v = *(const float4*)(row + j4);
        *(float4*)(buf + j4) = v;
        mv = fmaxf(mv, fmaxf(fmaxf(v.x, v.y), fmaxf(v.z, v.w)));
    }
    mv = warpMax(mv);
    __shared__ float shm[8];
    __shared__ float bc;
    if ((t & 31) == 0) shm[t >> 5] = mv;
    __syncthreads();
    if (t == 0) {
        float mm = shm[0];
#pragma unroll
        for (int w = 1; w < 8; w++) mm = fmaxf(mm, shm[w]);
        bc = fmaxf((mm - diag) * inv_tau, old_b);
    }
    __syncthreads();
    const float new_b = bc;

    float S = 0.f, E1 = 0.f, E2 = 0.f;
    for (int j = t; j < B_SZ; j += 256) {
        float d = buf[j] - diag;
        float x = d * inv_tau;
        float e = __expf(x - new_b);
        S += e; E1 += e * d; E2 += e * x;
    }
    S = warpSum(S); E1 = warpSum(E1); E2 = warpSum(E2);
    __shared__ float shS[8], sh1[8], sh2[8];
    if ((t & 31) == 0) { shS[t >> 5] = S; sh1[t >> 5] = E1; sh2[t >> 5] = E2; }
    __syncthreads();
    if (t == 0) {
        float sS = 0, s1 = 0, s2 = 0;
#pragma unroll
        for (int w = 0; w < 8; w++) { sS += shS[w]; s1 += sh1[w]; s2 += sh2[w]; }
        const float rinv = 1.0f / (float)(B_SZ - 1);
        float gI = sS * rinv;
        float s_new = (1.0f - GAMMA_S) * s_I[id] * __expf(old_b - new_b) + GAMMA_S * gI;
        float denom = s_new + EPSV;
        float loss = s1 / denom * rinv;
        float grad = logf(s_new) + new_b + RHO - s2 / denom * rinv;
        float gcl = fminf(fmaxf(grad, -GRAD_CLIP), GRAD_CLIP);
        float u_new = (1.0f - GAMMA_U) * u_I[id] + GAMMA_U * gcl;
        float eta = eta_from(ep, mep);
        float tau_new = fminf(fmaxf(tau - eta * u_new, TAU_MINV), TAU_MAXV);

        out[i] = gI;
        out[2 * B_SZ + i] = grad;
        g_loss_I[i] = loss;
        const size_t SB = 4 * B_SZ + 3;
        out[SB + (size_t)id] = s_new;
        out[SB + 2 * (size_t)N + id] = u_new;
        out[SB + 4 * (size_t)N + id] = new_b;
        out[SB + 6 * (size_t)N + id] = tau_new;
    }
}

__global__ __launch_bounds__(1024) void col_kernel(
        const float* __restrict__ tau_T, const float* __restrict__ b_T,
        const float* __restrict__ s_T, const float* __restrict__ u_T,
        const int* __restrict__ text_ids,
        const int* __restrict__ ep, const int* __restrict__ mep,
        float* __restrict__ out, int N) {
    const int tx = threadIdx.x;
    const int ty = threadIdx.y;
    const int j = blockIdx.x * 32 + tx;
    const int id = text_ids[j];
    const float tau = tau_T[id];
    const float inv_tau = 1.0f / tau;
    const float diag = g_sim[(size_t)j * B_SZ + j];
    const float old_b = b_T[id];

    float m = -FLT_MAX, S = 0.f, E1 = 0.f, E2 = 0.f;
    for (int r = ty; r < B_SZ; r += 32) {
        float d = g_sim[(size_t)r * B_SZ + j] - diag;
        float x = d * inv_tau;
        if (x > m) {
            float sc = __expf(m - x);
            S = S * sc + 1.0f;
            E1 = E1 * sc + d;
            E2 = E2 * sc + x;
            m = x;
        } else {
            float e = __expf(x - m);
            S += e; E1 += e * d; E2 += e * x;
        }
    }

    __shared__ float sm[32][33], sS[32][33], s1m[32][33], s2m[32][33];
    sm[ty][tx] = m; sS[ty][tx] = S; s1m[ty][tx] = E1; s2m[ty][tx] = E2;
    __syncthreads();

    if (ty == 0) {
        float M = -FLT_MAX;
#pragma unroll
        for (int k = 0; k < 32; k++) M = fmaxf(M, sm[k][tx]);
        const float new_b = fmaxf(M, old_b);
        float Ss = 0.f, e1 = 0.f, e2 = 0.f;
#pragma unroll
        for (int k = 0; k < 32; k++) {
            float sc = __expf(sm[k][tx] - new_b);
            Ss += sS[k][tx] * sc;
            e1 += s1m[k][tx] * sc;
            e2 += s2m[k][tx] * sc;
        }
        const float rinv = 1.0f / (float)(B_SZ - 1);
        float gT = Ss * rinv;
        float s_new = (1.0f - GAMMA_S) * s_T[id] * __expf(old_b - new_b) + GAMMA_S * gT;
        float denom = s_new + EPSV;
        float loss = e1 / denom * rinv;
        float grad = logf(s_new) + new_b + RHO - e2 / denom * rinv;
        float gcl = fminf(fmaxf(grad, -GRAD_CLIP), GRAD_CLIP);
        float u_new = (1.0f - GAMMA_U) * u_T[id] + GAMMA_U * gcl;
        float eta = eta_from(ep, mep);
        float tau_new = fminf(fmaxf(tau - eta * u_new, TAU_MINV), TAU_MAXV);

        out[B_SZ + j] = gT;
        out[3 * B_SZ + j] = grad;
        g_loss_T[j] = loss;
        const size_t SB = 4 * B_SZ + 3;
        out[SB + (size_t)N + id] = s_new;
        out[SB + 3 * (size_t)N + id] = u_new;
        out[SB + 5 * (size_t)N + id] = new_b;
        out[SB + 7 * (size_t)N + id] = tau_new;
    }
}

__global__ void finalize_kernel(const float* __restrict__ tau_I, const float* __restrict__ tau_T,
                                const int* __restrict__ iid, const int* __restrict__ tid_,
                                float* __restrict__ out) {
    const int t = threadIdx.x;  // 1024
    float lI = 0, lT = 0, tI = 0, tT = 0;
    for (int i = t; i < B_SZ; i += 1024) {
        lI += g_loss_I[i];
        lT += g_loss_T[i];
        tI += tau_I[iid[i]];
        tT += tau_T[tid_[i]];
    }
    lI = warpSum(lI); lT = warpSum(lT); tI = warpSum(tI); tT = warpSum(tT);
    __shared__ float sh[32][4];
    if ((t & 31) == 0) {
        int w = t >> 5;
        sh[w][0] = lI; sh[w][1] = lT; sh[w][2] = tI; sh[w][3] = tT;
    }
    __syncthreads();
    if (t == 0) {
        float a = 0, b = 0, c = 0, d = 0;
        for (int w = 0; w < 32; w++) { a += sh[w][0]; b += sh[w][1]; c += sh[w][2]; d += sh[w][3]; }
        const float invB = 1.0f / (float)B_SZ;
        out[4 * B_SZ + 0] = a * invB + b * invB;
        out[4 * B_SZ + 1] = c * invB;
        out[4 * B_SZ + 2] = d * invB;
    }
}

extern "C" void kernel_launch(void* const* d_in, const int* in_sizes, int n_in,
                              void* d_out, int out_size) {
    const float* imf   = (const float*)d_in[0];
    const float* txf   = (const float*)d_in[1];
    const float* s_I   = (const float*)d_in[2];
    const float* s_T   = (const float*)d_in[3];
    const float* tau_I = (const float*)d_in[4];
    const float* tau_T = (const float*)d_in[5];
    const float* u_I   = (const float*)d_in[6];
    const float* u_T   = (const float*)d_in[7];
    const float* b_I   = (const float*)d_in[8];
    const float* b_T   = (const float*)d_in[9];
    const int* iid     = (const int*)d_in[10];
    const int* tid     = (const int*)d_in[11];
    const int* ep      = (const int*)d_in[12];
    const int* mep     = (const int*)d_in[13];
    float* out = (float*)d_out;
    const int N = in_sizes[2];  // 2,900,000

    // 1) fp32 -> (fp16 hi, fp16 lo) split
    convert_kernel<<<2048, 256>>>(imf, txf);

    // 2) 3xFP16 mma.sync GEMM -> g_sim
    gemm_fp16<<<dim3(B_SZ / 128, B_SZ / 128), 256>>>();

    // 3) bulk copy state arrays to output
    copy8_kernel<<<dim3(1024, 8), 256>>>(s_I, s_T, u_I, u_T, b_I, b_T, tau_I, tau_T,
                                         out + 4 * B_SZ + 3, N);

    // 4) row (image) pass
    row_kernel<<<B_SZ, 256>>>(tau_I, b_I, s_I, u_I, iid, ep, mep, out, N);

    // 5) column (text) pass
    col_kernel<<<B_SZ / 32, dim3(32, 32)>>>(tau_T, b_T, s_T, u_T, tid, ep, mep, out, N);

    // 6) scalars
    finalize_kernel<<<1, 1024>>>(tau_I, tau_T, iid, tid, out);
}

// round 16
// speedup vs baseline: 2.3715x; 1.1219x over previous
#include <cuda_runtime.h>
#include <cuda_fp16.h>
#include <math.h>
#include <stdint.h>
#include <float.h>

#define B_SZ 4096
#define DIM  1024
#define GAMMA_S 0.8f
#define GAMMA_U 0.8f
#define RHO     0.1f
#define EPSV    1e-10f
#define TAU_MINV 0.005f
#define TAU_MAXV 1.0f
#define GRAD_CLIP 5.0f
#define ETA_INIT 0.01f
#define ETA_MINV 0.0001f

// Scratch: sim matrix (64MB) + fp16 split operands (32MB) + loss vectors.
__device__ float g_sim[B_SZ * B_SZ];
__device__ float g_loss_I[B_SZ];
__device__ float g_loss_T[B_SZ];
__device__ __half g_Ahi[B_SZ * DIM];
__device__ __half g_Alo[B_SZ * DIM];
__device__ __half g_Bhi[B_SZ * DIM];
__device__ __half g_Blo[B_SZ * DIM];

__device__ __forceinline__ float warpMax(float v) {
#pragma unroll
    for (int o = 16; o > 0; o >>= 1) v = fmaxf(v, __shfl_xor_sync(0xffffffffu, v, o));
    return v;
}
__device__ __forceinline__ float warpSum(float v) {
#pragma unroll
    for (int o = 16; o > 0; o >>= 1) v += __shfl_xor_sync(0xffffffffu, v, o);
    return v;
}

// ───────────────────── split-fp16 convert pre-pass ─────────────────────
__global__ __launch_bounds__(256) void convert_kernel(const float* __restrict__ imf,
                                                      const float* __restrict__ txf) {
    const int n4 = B_SZ * DIM / 4;
    for (int i = blockIdx.x * blockDim.x + threadIdx.x; i < n4;
         i += gridDim.x * blockDim.x) {
        float4 a = ((const float4*)imf)[i];
        float4 b = ((const float4*)txf)[i];
        float av[4] = {a.x, a.y, a.z, a.w};
        float bv[4] = {b.x, b.y, b.z, b.w};
        __half2* ah = (__half2*)g_Ahi + i * 2;
        __half2* al = (__half2*)g_Alo + i * 2;
        __half2* bh = (__half2*)g_Bhi + i * 2;
        __half2* bl = (__half2*)g_Blo + i * 2;
        __half hi[4], lo[4], hib[4], lob[4];
#pragma unroll
        for (int q = 0; q < 4; q++) {
            hi[q]  = __float2half_rn(av[q]);
            lo[q]  = __float2half_rn(av[q] - __half2float(hi[q]));
            hib[q] = __float2half_rn(bv[q]);
            lob[q] = __float2half_rn(bv[q] - __half2float(hib[q]));
        }
        ah[0] = __halves2half2(hi[0], hi[1]);   ah[1] = __halves2half2(hi[2], hi[3]);
        al[0] = __halves2half2(lo[0], lo[1]);   al[1] = __halves2half2(lo[2], lo[3]);
        bh[0] = __halves2half2(hib[0], hib[1]); bh[1] = __halves2half2(hib[2], hib[3]);
        bl[0] = __halves2half2(lob[0], lob[1]); bl[1] = __halves2half2(lob[2], lob[3]);
    }
}

// ───────────── 3xFP16 mma.sync GEMM with cp.async + ldmatrix ─────────────
// CTA 128x128, BK=32 halves, 256 threads (8 warps: 2M x 4N, warp 64x32),
// double-buffered dynamic smem, m16n8k16.f16 fp32-accum, hi/lo 3-product.
__device__ __forceinline__ void mma16(float* c, const uint32_t* a, const uint32_t* b) {
    asm volatile(
        "mma.sync.aligned.m16n8k16.row.col.f32.f16.f16.f32 "
        "{%0,%1,%2,%3},{%4,%5,%6,%7},{%8,%9},{%0,%1,%2,%3};\n"
        : "+f"(c[0]), "+f"(c[1]), "+f"(c[2]), "+f"(c[3])
        : "r"(a[0]), "r"(a[1]), "r"(a[2]), "r"(a[3]), "r"(b[0]), "r"(b[1]));
}
__device__ __forceinline__ void ldsm4(uint32_t* r, uint32_t addr) {
    asm volatile("ldmatrix.sync.aligned.m8n8.x4.shared.b16 {%0,%1,%2,%3}, [%4];"
                 : "=r"(r[0]), "=r"(r[1]), "=r"(r[2]), "=r"(r[3]) : "r"(addr));
}
__device__ __forceinline__ uint32_t smem_u32(const void* p) {
    uint32_t a;
    asm("{ .reg .u64 t; cvta.to.shared.u64 t, %1; cvt.u32.u64 %0, t; }" : "=r"(a) : "l"(p));
    return a;
}
__device__ __forceinline__ void cp16(uint32_t dst, const void* src) {
    asm volatile("cp.async.ca.shared.global [%0], [%1], 16;" :: "r"(dst), "l"(src));
}
#define CP_COMMIT() asm volatile("cp.async.commit_group;" ::: "memory")
#define CP_WAIT1()  asm volatile("cp.async.wait_group 1;" ::: "memory")

#define BKH 32                        // k halves per chunk
#define NCH (DIM / BKH)               // 32 chunks
#define LDH 40                        // padded smem row stride (halves)
#define ARR_B (128 * LDH * 2)         // 10240 bytes per operand array
#define BUF_B (4 * ARR_B)             // 40960 bytes per buffer
#define A_HI 0
#define A_LO ARR_B
#define B_HI (2 * ARR_B)
#define B_LO (3 * ARR_B)

__global__ __launch_bounds__(256) void gemm_fp16(void) {
    extern __shared__ char smc[];
    const uint32_t sb = smem_u32(smc);

    const int t = threadIdx.x;
    const int m0 = blockIdx.y * 128, n0 = blockIdx.x * 128;
    const int wid = t >> 5, lane = t & 31;
    const int wm = (wid & 1) * 64;     // warp row base
    const int wn = (wid >> 1) * 32;    // warp col base

    float c[4][4][4];
#pragma unroll
    for (int mt = 0; mt < 4; mt++)
#pragma unroll
        for (int nt = 0; nt < 4; nt++)
#pragma unroll
            for (int q = 0; q < 4; q++) c[mt][nt][q] = 0.0f;

    // cp.async mapping: thread covers rows (t>>2) and (t>>2)+64, 16B col t&3
    const int lr = t >> 2;
    const int lc = t & 3;

    // ldmatrix address components
    const int fr = lane & 15;                 // fragment row 0..15
    const int fk = (lane >> 4) << 3;          // 0 or 8 (k halves)

    // Pipeline: issue chunk kc (kc<NCH), compute chunk kc-1 (kc>=1).
    // NCH+1 iterations total -> computes exactly chunks 0..NCH-1.
    for (int kc = 0; kc <= NCH; kc++) {
        if (kc < NCH) {
            const uint32_t dst = sb + (kc & 1) * BUF_B;
#pragma unroll
            for (int v = 0; v < 2; v++) {
                const int row = lr + v * 64;
                const uint32_t doff = (uint32_t)(row * (LDH * 2) + lc * 16);
                const size_t ga = (size_t)(m0 + row) * DIM + kc * BKH + lc * 8;
                const size_t gb = (size_t)(n0 + row) * DIM + kc * BKH + lc * 8;
                cp16(dst + A_HI + doff, g_Ahi + ga);
                cp16(dst + A_LO + doff, g_Alo + ga);
                cp16(dst + B_HI + doff, g_Bhi + gb);
                cp16(dst + B_LO + doff, g_Blo + gb);
            }
        }
        CP_COMMIT();
        if (kc < 1) continue;          // need one chunk in flight before compute

        const int cc_ = kc - 1;        // chunk to compute (0..NCH-1)
        CP_WAIT1();                    // chunk cc_ is complete
        __syncthreads();

        const uint32_t base = sb + (cc_ & 1) * BUF_B;
#pragma unroll
        for (int ks = 0; ks < 2; ks++) {
            const uint32_t koff = (uint32_t)((ks * 16 + fk) * 2);
            uint32_t ah[4][4], al[4][4], bh[4][2], bl[4][2];
#pragma unroll
            for (int mt = 0; mt < 4; mt++) {
                const uint32_t ro = (uint32_t)((wm + mt * 16 + fr) * (LDH * 2)) + koff;
                ldsm4(ah[mt], base + A_HI + ro);
                ldsm4(al[mt], base + A_LO + ro);
            }
#pragma unroll
            for (int p = 0; p < 2; p++) {
                const uint32_t ro = (uint32_t)((wn + p * 16 + fr) * (LDH * 2)) + koff;
                uint32_t tmp[4];
                ldsm4(tmp, base + B_HI + ro);
                bh[2 * p][0] = tmp[0]; bh[2 * p + 1][0] = tmp[1];
                bh[2 * p][1] = tmp[2]; bh[2 * p + 1][1] = tmp[3];
                ldsm4(tmp, base + B_LO + ro);
                bl[2 * p][0] = tmp[0]; bl[2 * p + 1][0] = tmp[1];
                bl[2 * p][1] = tmp[2]; bl[2 * p + 1][1] = tmp[3];
            }
#pragma unroll
            for (int mt = 0; mt < 4; mt++)
#pragma unroll
                for (int nt = 0; nt < 4; nt++) {
                    mma16(c[mt][nt], ah[mt], bh[nt]);
                    mma16(c[mt][nt], ah[mt], bl[nt]);
                    mma16(c[mt][nt], al[mt], bh[nt]);
                }
        }
        __syncthreads();               // all reads of this buffer done before reuse
    }

    // epilogue: c layout m16n8 -> rows gp/gp+8, cols 2*tg..+1
    const int gp = lane >> 2, tg = lane & 3;
#pragma unroll
    for (int mt = 0; mt < 4; mt++) {
        const int rr = m0 + wm + mt * 16 + gp;
#pragma unroll
        for (int nt = 0; nt < 4; nt++) {
            const int cc = n0 + wn + nt * 8 + tg * 2;
            *(float2*)(g_sim + (size_t)rr * B_SZ + cc) =
                make_float2(c[mt][nt][0], c[mt][nt][1]);
            *(float2*)(g_sim + (size_t)(rr + 8) * B_SZ + cc) =
                make_float2(c[mt][nt][2], c[mt][nt][3]);
        }
    }
}

// ───────────────────── elementwise / reduction kernels ─────────────────────
__global__ void copy8_kernel(const float* __restrict__ a0, const float* __restrict__ a1,
                             const float* __restrict__ a2, const float* __restrict__ a3,
                             const float* __restrict__ a4, const float* __restrict__ a5,
                             const float* __restrict__ a6, const float* __restrict__ a7,
                             float* __restrict__ dst, int n) {
    const float* srcs[8] = {a0, a1, a2, a3, a4, a5, a6, a7};
    const float* s = srcs[blockIdx.y];
    float* d = dst + (size_t)blockIdx.y * n;
    for (int i = blockIdx.x * blockDim.x + threadIdx.x; i < n;
         i += gridDim.x * blockDim.x)
        d[i] = s[i];
}

__device__ __forceinline__ float eta_from(const int* ep, const int* mep) {
    float f = (float)ep[0] / (float)mep[0];
    return ETA_MINV + (ETA_INIT - ETA_MINV) * cosf(1.57079632679f * f);
}

__global__ __launch_bounds__(256) void row_kernel(
        const float* __restrict__ tau_I, const float* __restrict__ b_I,
        const float* __restrict__ s_I, const float* __restrict__ u_I,
        const int* __restrict__ image_ids,
        const int* __restrict__ ep, const int* __restrict__ mep,
        float* __restrict__ out, int N) {
    __shared__ float buf[B_SZ];
    const int i = blockIdx.x;
    const int t = threadIdx.x;  // 256
    const float* row = g_sim + (size_t)i * B_SZ;
    const int id = image_ids[i];
    const float tau = tau_I[id];
    const float inv_tau = 1.0f / tau;
    const float diag = row[i];
    const float old_b = b_I[id];

    float mv = -FLT_MAX;
#pragma unroll
    for (int q = 0; q < 4; q++) {
        int j4 = (t + q * 256) * 4;
        float4 v = *(const float4*)(row + j4);
        *(float4*)(buf + j4) = v;
        mv = fmaxf(mv, fmaxf(fmaxf(v.x, v.y), fmaxf(v.z, v.w)));
    }
    mv = warpMax(mv);
    __shared__ float shm[8];
    __shared__ float bc;
    if ((t & 31) == 0) shm[t >> 5] = mv;
    __syncthreads();
    if (t == 0) {
        float mm = shm[0];
#pragma unroll
        for (int w = 1; w < 8; w++) mm = fmaxf(mm, shm[w]);
        bc = fmaxf((mm - diag) * inv_tau, old_b);
    }
    __syncthreads();
    const float new_b = bc;

    float S = 0.f, E1 = 0.f, E2 = 0.f;
    for (int j = t; j < B_SZ; j += 256) {
        float d = buf[j] - diag;
        float x = d * inv_tau;
        float e = __expf(x - new_b);
        S += e; E1 += e * d; E2 += e * x;
    }
    S = warpSum(S); E1 = warpSum(E1); E2 = warpSum(E2);
    __shared__ float shS[8], sh1[8], sh2[8];
    if ((t & 31) == 0) { shS[t >> 5] = S; sh1[t >> 5] = E1; sh2[t >> 5] = E2; }
    __syncthreads();
    if (t == 0) {
        float sS = 0, s1 = 0, s2 = 0;
#pragma unroll
        for (int w = 0; w < 8; w++) { sS += shS[w]; s1 += sh1[w]; s2 += sh2[w]; }
        const float rinv = 1.0f / (float)(B_SZ - 1);
        float gI = sS * rinv;
        float s_new = (1.0f - GAMMA_S) * s_I[id] * __expf(old_b - new_b) + GAMMA_S * gI;
        float denom = s_new + EPSV;
        float loss = s1 / denom * rinv;
        float grad = logf(s_new) + new_b + RHO - s2 / denom * rinv;
        float gcl = fminf(fmaxf(grad, -GRAD_CLIP), GRAD_CLIP);
        float u_new = (1.0f - GAMMA_U) * u_I[id] + GAMMA_U * gcl;
        float eta = eta_from(ep, mep);
        float tau_new = fminf(fmaxf(tau - eta * u_new, TAU_MINV), TAU_MAXV);

        out[i] = gI;
        out[2 * B_SZ + i] = grad;
        g_loss_I[i] = loss;
        const size_t SB = 4 * B_SZ + 3;
        out[SB + (size_t)id] = s_new;
        out[SB + 2 * (size_t)N + id] = u_new;
        out[SB + 4 * (size_t)N + id] = new_b;
        out[SB + 6 * (size_t)N + id] = tau_new;
    }
}

__global__ __launch_bounds__(1024) void col_kernel(
        const float* __restrict__ tau_T, const float* __restrict__ b_T,
        const float* __restrict__ s_T, const float* __restrict__ u_T,
        const int* __restrict__ text_ids,
        const int* __restrict__ ep, const int* __restrict__ mep,
        float* __restrict__ out, int N) {
    const int tx = threadIdx.x;
    const int ty = threadIdx.y;
    const int j = blockIdx.x * 32 + tx;
    const int id = text_ids[j];
    const float tau = tau_T[id];
    const float inv_tau = 1.0f / tau;
    const float diag = g_sim[(size_t)j * B_SZ + j];
    const float old_b = b_T[id];

    float m = -FLT_MAX, S = 0.f, E1 = 0.f, E2 = 0.f;
    for (int r = ty; r < B_SZ; r += 32) {
        float d = g_sim[(size_t)r * B_SZ + j] - diag;
        float x = d * inv_tau;
        if (x > m) {
            float sc = __expf(m - x);
            S = S * sc + 1.0f;
            E1 = E1 * sc + d;
            E2 = E2 * sc + x;
            m = x;
        } else {
            float e = __expf(x - m);
            S += e; E1 += e * d; E2 += e * x;
        }
    }

    __shared__ float sm[32][33], sS[32][33], s1m[32][33], s2m[32][33];
    sm[ty][tx] = m; sS[ty][tx] = S; s1m[ty][tx] = E1; s2m[ty][tx] = E2;
    __syncthreads();

    if (ty == 0) {
        float M = -FLT_MAX;
#pragma unroll
        for (int k = 0; k < 32; k++) M = fmaxf(M, sm[k][tx]);
        const float new_b = fmaxf(M, old_b);
        float Ss = 0.f, e1 = 0.f, e2 = 0.f;
#pragma unroll
        for (int k = 0; k < 32; k++) {
            float sc = __expf(sm[k][tx] - new_b);
            Ss += sS[k][tx] * sc;
            e1 += s1m[k][tx] * sc;
            e2 += s2m[k][tx] * sc;
        }
        const float rinv = 1.0f / (float)(B_SZ - 1);
        float gT = Ss * rinv;
        float s_new = (1.0f - GAMMA_S) * s_T[id] * __expf(old_b - new_b) + GAMMA_S * gT;
        float denom = s_new + EPSV;
        float loss = e1 / denom * rinv;
        float grad = logf(s_new) + new_b + RHO - e2 / denom * rinv;
        float gcl = fminf(fmaxf(grad, -GRAD_CLIP), GRAD_CLIP);
        float u_new = (1.0f - GAMMA_U) * u_T[id] + GAMMA_U * gcl;
        float eta = eta_from(ep, mep);
        float tau_new = fminf(fmaxf(tau - eta * u_new, TAU_MINV), TAU_MAXV);

        out[B_SZ + j] = gT;
        out[3 * B_SZ + j] = grad;
        g_loss_T[j] = loss;
        const size_t SB = 4 * B_SZ + 3;
        out[SB + (size_t)N + id] = s_new;
        out[SB + 3 * (size_t)N + id] = u_new;
        out[SB + 5 * (size_t)N + id] = new_b;
        out[SB + 7 * (size_t)N + id] = tau_new;
    }
}

__global__ void finalize_kernel(const float* __restrict__ tau_I, const float* __restrict__ tau_T,
                                const int* __restrict__ iid, const int* __restrict__ tid_,
                                float* __restrict__ out) {
    const int t = threadIdx.x;  // 1024
    float lI = 0, lT = 0, tI = 0, tT = 0;
    for (int i = t; i < B_SZ; i += 1024) {
        lI += g_loss_I[i];
        lT += g_loss_T[i];
        tI += tau_I[iid[i]];
        tT += tau_T[tid_[i]];
    }
    lI = warpSum(lI); lT = warpSum(lT); tI = warpSum(tI); tT = warpSum(tT);
    __shared__ float sh[32][4];
    if ((t & 31) == 0) {
        int w = t >> 5;
        sh[w][0] = lI; sh[w][1] = lT; sh[w][2] = tI; sh[w][3] = tT;
    }
    __syncthreads();
    if (t == 0) {
        float a = 0, b = 0, c = 0, d = 0;
        for (int w = 0; w < 32; w++) { a += sh[w][0]; b += sh[w][1]; c += sh[w][2]; d += sh[w][3]; }
        const float invB = 1.0f / (float)B_SZ;
        out[4 * B_SZ + 0] = a * invB + b * invB;
        out[4 * B_SZ + 1] = c * invB;
        out[4 * B_SZ + 2] = d * invB;
    }
}

extern "C" void kernel_launch(void* const* d_in, const int* in_sizes, int n_in,
                              void* d_out, int out_size) {
    const float* imf   = (const float*)d_in[0];
    const float* txf   = (const float*)d_in[1];
    const float* s_I   = (const float*)d_in[2];
    const float* s_T   = (const float*)d_in[3];
    const float* tau_I = (const float*)d_in[4];
    const float* tau_T = (const float*)d_in[5];
    const float* u_I   = (const float*)d_in[6];
    const float* u_T   = (const float*)d_in[7];
    const float* b_I   = (const float*)d_in[8];
    const float* b_T   = (const float*)d_in[9];
    const int* iid     = (const int*)d_in[10];
    const int* tid     = (const int*)d_in[11];
    const int* ep      = (const int*)d_in[12];
    const int* mep     = (const int*)d_in[13];
    float* out = (float*)d_out;
    const int N = in_sizes[2];  // 2,900,000

    static int smem_set = 0;
    if (!smem_set) {
        cudaFuncSetAttribute(gemm_fp16, cudaFuncAttributeMaxDynamicSharedMemorySize,
                             2 * BUF_B);
        smem_set = 1;
    }

    // 1) fp32 -> (fp16 hi, fp16 lo) split
    convert_kernel<<<2048, 256>>>(imf, txf);

    // 2) 3xFP16 mma.sync GEMM (cp.async + ldmatrix, double-buffered) -> g_sim
    gemm_fp16<<<dim3(B_SZ / 128, B_SZ / 128), 256, 2 * BUF_B>>>();

    // 3) bulk copy state arrays to output
    copy8_kernel<<<dim3(1024, 8), 256>>>(s_I, s_T, u_I, u_T, b_I, b_T, tau_I, tau_T,
                                         out + 4 * B_SZ + 3, N);

    // 4) row (image) pass
    row_kernel<<<B_SZ, 256>>>(tau_I, b_I, s_I, u_I, iid, ep, mep, out, N);

    // 5) column (text) pass
    col_kernel<<<B_SZ / 32, dim3(32, 32)>>>(tau_T, b_T, s_T, u_T, tid, ep, mep, out, N);

    // 6) scalars
    finalize_kernel<<<1, 1024>>>(tau_I, tau_T, iid, tid, out);
}

// round 17
// speedup vs baseline: 2.4272x; 1.0235x over previous
#include <cuda_runtime.h>
#include <cuda_fp16.h>
#include <math.h>
#include <stdint.h>
#include <float.h>

#define B_SZ 4096
#define DIM  1024
#define GAMMA_S 0.8f
#define GAMMA_U 0.8f
#define RHO     0.1f
#define EPSV    1e-10f
#define TAU_MINV 0.005f
#define TAU_MAXV 1.0f
#define GRAD_CLIP 5.0f
#define ETA_INIT 0.01f
#define ETA_MINV 0.0001f

// Scratch: sim matrix (64MB) + fp16 split operands (32MB) + loss vectors.
__device__ float g_sim[B_SZ * B_SZ];
__device__ float g_loss_I[B_SZ];
__device__ float g_loss_T[B_SZ];
__device__ __half g_Ahi[B_SZ * DIM];
__device__ __half g_Alo[B_SZ * DIM];
__device__ __half g_Bhi[B_SZ * DIM];
__device__ __half g_Blo[B_SZ * DIM];

__device__ __forceinline__ float warpMax(float v) {
#pragma unroll
    for (int o = 16; o > 0; o >>= 1) v = fmaxf(v, __shfl_xor_sync(0xffffffffu, v, o));
    return v;
}
__device__ __forceinline__ float warpSum(float v) {
#pragma unroll
    for (int o = 16; o > 0; o >>= 1) v += __shfl_xor_sync(0xffffffffu, v, o);
    return v;
}

// ───── convert (fp32 -> fp16 hi/lo) fused with bulk state copy ─────
__global__ __launch_bounds__(256) void convert_copy_kernel(
        const float* __restrict__ imf, const float* __restrict__ txf,
        const float* __restrict__ a0, const float* __restrict__ a1,
        const float* __restrict__ a2, const float* __restrict__ a3,
        const float* __restrict__ a4, const float* __restrict__ a5,
        const float* __restrict__ a6, const float* __restrict__ a7,
        float* __restrict__ dst, int n) {
    const int gid = blockIdx.x * blockDim.x + threadIdx.x;
    const int gsz = gridDim.x * blockDim.x;

    const int n4 = B_SZ * DIM / 4;
    for (int i = gid; i < n4; i += gsz) {
        float4 a = ((const float4*)imf)[i];
        float4 b = ((const float4*)txf)[i];
        float av[4] = {a.x, a.y, a.z, a.w};
        float bv[4] = {b.x, b.y, b.z, b.w};
        __half2* ah = (__half2*)g_Ahi + i * 2;
        __half2* al = (__half2*)g_Alo + i * 2;
        __half2* bh = (__half2*)g_Bhi + i * 2;
        __half2* bl = (__half2*)g_Blo + i * 2;
        __half hi[4], lo[4], hib[4], lob[4];
#pragma unroll
        for (int q = 0; q < 4; q++) {
            hi[q]  = __float2half_rn(av[q]);
            lo[q]  = __float2half_rn(av[q] - __half2float(hi[q]));
            hib[q] = __float2half_rn(bv[q]);
            lob[q] = __float2half_rn(bv[q] - __half2float(hib[q]));
        }
        ah[0] = __halves2half2(hi[0], hi[1]);   ah[1] = __halves2half2(hi[2], hi[3]);
        al[0] = __halves2half2(lo[0], lo[1]);   al[1] = __halves2half2(lo[2], lo[3]);
        bh[0] = __halves2half2(hib[0], hib[1]); bh[1] = __halves2half2(hib[2], hib[3]);
        bl[0] = __halves2half2(lob[0], lob[1]); bl[1] = __halves2half2(lob[2], lob[3]);
    }

    // bulk copy of the 8 state arrays (dst base is out+4*B_SZ+3)
    const float* srcs[8] = {a0, a1, a2, a3, a4, a5, a6, a7};
#pragma unroll
    for (int k = 0; k < 8; k++) {
        const float* s = srcs[k];
        float* d = dst + (size_t)k * n;
        for (int i = gid; i < n; i += gsz) d[i] = s[i];
    }
}

// ───────── 3xFP16 mma.sync GEMM, 3-stage cp.async pipeline ─────────
// CTA 128x128, BK=32 halves, 256 threads (8 warps: 2M x 4N, warp 64x32),
// triple-buffered dynamic smem, ONE __syncthreads per chunk.
__device__ __forceinline__ void mma16(float* c, const uint32_t* a, const uint32_t* b) {
    asm volatile(
        "mma.sync.aligned.m16n8k16.row.col.f32.f16.f16.f32 "
        "{%0,%1,%2,%3},{%4,%5,%6,%7},{%8,%9},{%0,%1,%2,%3};\n"
        : "+f"(c[0]), "+f"(c[1]), "+f"(c[2]), "+f"(c[3])
        : "r"(a[0]), "r"(a[1]), "r"(a[2]), "r"(a[3]), "r"(b[0]), "r"(b[1]));
}
__device__ __forceinline__ void ldsm4(uint32_t* r, uint32_t addr) {
    asm volatile("ldmatrix.sync.aligned.m8n8.x4.shared.b16 {%0,%1,%2,%3}, [%4];"
                 : "=r"(r[0]), "=r"(r[1]), "=r"(r[2]), "=r"(r[3]) : "r"(addr));
}
__device__ __forceinline__ uint32_t smem_u32(const void* p) {
    uint32_t a;
    asm("{ .reg .u64 t; cvta.to.shared.u64 t, %1; cvt.u32.u64 %0, t; }" : "=r"(a) : "l"(p));
    return a;
}
__device__ __forceinline__ void cp16(uint32_t dst, const void* src) {
    asm volatile("cp.async.ca.shared.global [%0], [%1], 16;" :: "r"(dst), "l"(src));
}
#define CP_COMMIT() asm volatile("cp.async.commit_group;" ::: "memory")
#define CP_WAIT1()  asm volatile("cp.async.wait_group 1;" ::: "memory")

#define BKH 32                        // k halves per chunk
#define NCH (DIM / BKH)               // 32 chunks
#define LDH 40                        // padded smem row stride (halves)
#define ARR_B (128 * LDH * 2)         // 10240 bytes per operand array
#define BUF_B (4 * ARR_B)             // 40960 bytes per stage
#define NSTAGE 3
#define A_HI 0
#define A_LO ARR_B
#define B_HI (2 * ARR_B)
#define B_LO (3 * ARR_B)

__global__ __launch_bounds__(256) void gemm_fp16(void) {
    extern __shared__ char smc[];
    const uint32_t sb = smem_u32(smc);

    const int t = threadIdx.x;
    const int m0 = blockIdx.y * 128, n0 = blockIdx.x * 128;
    const int wid = t >> 5, lane = t & 31;
    const int wm = (wid & 1) * 64;     // warp row base
    const int wn = (wid >> 1) * 32;    // warp col base

    float c[4][4][4];
#pragma unroll
    for (int mt = 0; mt < 4; mt++)
#pragma unroll
        for (int nt = 0; nt < 4; nt++)
#pragma unroll
            for (int q = 0; q < 4; q++) c[mt][nt][q] = 0.0f;

    // cp.async mapping: thread covers rows (t>>2) and (t>>2)+64, 16B col t&3
    const int lr = t >> 2;
    const int lc = t & 3;
    const uint32_t doff0 = (uint32_t)(lr * (LDH * 2) + lc * 16);
    const uint32_t doff1 = (uint32_t)((lr + 64) * (LDH * 2) + lc * 16);

    // ldmatrix address components
    const int fr = lane & 15;                 // fragment row 0..15
    const int fk = (lane >> 4) << 3;          // 0 or 8 (k halves)

    // issue chunk kc into stage s
    auto issue = [&](int kc, uint32_t dst) {
        const size_t ga0 = (size_t)(m0 + lr) * DIM + kc * BKH + lc * 8;
        const size_t gb0 = (size_t)(n0 + lr) * DIM + kc * BKH + lc * 8;
        const size_t off64 = (size_t)64 * DIM;
        cp16(dst + A_HI + doff0, g_Ahi + ga0);
        cp16(dst + A_HI + doff1, g_Ahi + ga0 + off64);
        cp16(dst + A_LO + doff0, g_Alo + ga0);
        cp16(dst + A_LO + doff1, g_Alo + ga0 + off64);
        cp16(dst + B_HI + doff0, g_Bhi + gb0);
        cp16(dst + B_HI + doff1, g_Bhi + gb0 + off64);
        cp16(dst + B_LO + doff0, g_Blo + gb0);
        cp16(dst + B_LO + doff1, g_Blo + gb0 + off64);
    };

    // prologue: 2 chunks in flight
    issue(0, sb);            CP_COMMIT();
    issue(1, sb + BUF_B);    CP_COMMIT();

    int cur = 0;  // stage holding chunk j
    for (int j = 0; j < NCH; j++) {
        CP_WAIT1();          // chunk j landed
        __syncthreads();     // visible to all; prev compute of stage `cur` done

        const uint32_t base = sb + (uint32_t)cur * BUF_B;
#pragma unroll
        for (int ks = 0; ks < 2; ks++) {
            const uint32_t koff = (uint32_t)((ks * 16 + fk) * 2);
            uint32_t ah[4][4], al[4][4], bh[4][2], bl[4][2];
#pragma unroll
            for (int mt = 0; mt < 4; mt++) {
                const uint32_t ro = (uint32_t)((wm + mt * 16 + fr) * (LDH * 2)) + koff;
                ldsm4(ah[mt], base + A_HI + ro);
                ldsm4(al[mt], base + A_LO + ro);
            }
#pragma unroll
            for (int p = 0; p < 2; p++) {
                const uint32_t ro = (uint32_t)((wn + p * 16 + fr) * (LDH * 2)) + koff;
                uint32_t tmp[4];
                ldsm4(tmp, base + B_HI + ro);
                bh[2 * p][0] = tmp[0]; bh[2 * p + 1][0] = tmp[1];
                bh[2 * p][1] = tmp[2]; bh[2 * p + 1][1] = tmp[3];
                ldsm4(tmp, base + B_LO + ro);
                bl[2 * p][0] = tmp[0]; bl[2 * p + 1][0] = tmp[1];
                bl[2 * p][1] = tmp[2]; bl[2 * p + 1][1] = tmp[3];
            }
            // 3 sweeps of 16 independent mma -> accumulator RAW chains spaced by 16
#pragma unroll
            for (int mt = 0; mt < 4; mt++)
#pragma unroll
                for (int nt = 0; nt < 4; nt++) mma16(c[mt][nt], ah[mt], bh[nt]);
#pragma unroll
            for (int mt = 0; mt < 4; mt++)
#pragma unroll
                for (int nt = 0; nt < 4; nt++) mma16(c[mt][nt], ah[mt], bl[nt]);
#pragma unroll
            for (int mt = 0; mt < 4; mt++)
#pragma unroll
                for (int nt = 0; nt < 4; nt++) mma16(c[mt][nt], al[mt], bh[nt]);
        }

        // refill: chunk j+2 goes into the stage freed at iteration j-1,
        // protected by this iteration's __syncthreads.
        const int nk = j + 2;
        int ns = cur + 2; if (ns >= NSTAGE) ns -= NSTAGE;
        if (nk < NCH) issue(nk, sb + (uint32_t)ns * BUF_B);
        CP_COMMIT();
        cur = (cur + 1 == NSTAGE) ? 0 : cur + 1;
    }

    // epilogue: c layout m16n8 -> rows gp/gp+8, cols 2*tg..+1
    const int gp = lane >> 2, tg = lane & 3;
#pragma unroll
    for (int mt = 0; mt < 4; mt++) {
        const int rr = m0 + wm + mt * 16 + gp;
#pragma unroll
        for (int nt = 0; nt < 4; nt++) {
            const int cc = n0 + wn + nt * 8 + tg * 2;
            *(float2*)(g_sim + (size_t)rr * B_SZ + cc) =
                make_float2(c[mt][nt][0], c[mt][nt][1]);
            *(float2*)(g_sim + (size_t)(rr + 8) * B_SZ + cc) =
                make_float2(c[mt][nt][2], c[mt][nt][3]);
        }
    }
}

// ───────────────────── elementwise / reduction kernels ─────────────────────
__device__ __forceinline__ float eta_from(const int* ep, const int* mep) {
    float f = (float)ep[0] / (float)mep[0];
    return ETA_MINV + (ETA_INIT - ETA_MINV) * cosf(1.57079632679f * f);
}

__global__ __launch_bounds__(256) void row_kernel(
        const float* __restrict__ tau_I, const float* __restrict__ b_I,
        const float* __restrict__ s_I, const float* __restrict__ u_I,
        const int* __restrict__ image_ids,
        const int* __restrict__ ep, const int* __restrict__ mep,
        float* __restrict__ out, int N) {
    __shared__ float buf[B_SZ];
    const int i = blockIdx.x;
    const int t = threadIdx.x;  // 256
    const float* row = g_sim + (size_t)i * B_SZ;
    const int id = image_ids[i];
    const float tau = tau_I[id];
    const float inv_tau = 1.0f / tau;
    const float diag = row[i];
    const float old_b = b_I[id];

    float mv = -FLT_MAX;
#pragma unroll
    for (int q = 0; q < 4; q++) {
        int j4 = (t + q * 256) * 4;
        float4 v = *(const float4*)(row + j4);
        *(float4*)(buf + j4) = v;
        mv = fmaxf(mv, fmaxf(fmaxf(v.x, v.y), fmaxf(v.z, v.w)));
    }
    mv = warpMax(mv);
    __shared__ float shm[8];
    __shared__ float bc;
    if ((t & 31) == 0) shm[t >> 5] = mv;
    __syncthreads();
    if (t == 0) {
        float mm = shm[0];
#pragma unroll
        for (int w = 1; w < 8; w++) mm = fmaxf(mm, shm[w]);
        bc = fmaxf((mm - diag) * inv_tau, old_b);
    }
    __syncthreads();
    const float new_b = bc;

    float S = 0.f, E1 = 0.f, E2 = 0.f;
    for (int j = t; j < B_SZ; j += 256) {
        float d = buf[j] - diag;
        float x = d * inv_tau;
        float e = __expf(x - new_b);
        S += e; E1 += e * d; E2 += e * x;
    }
    S = warpSum(S); E1 = warpSum(E1); E2 = warpSum(E2);
    __shared__ float shS[8], sh1[8], sh2[8];
    if ((t & 31) == 0) { shS[t >> 5] = S; sh1[t >> 5] = E1; sh2[t >> 5] = E2; }
    __syncthreads();
    if (t == 0) {
        float sS = 0, s1 = 0, s2 = 0;
#pragma unroll
        for (int w = 0; w < 8; w++) { sS += shS[w]; s1 += sh1[w]; s2 += sh2[w]; }
        const float rinv = 1.0f / (float)(B_SZ - 1);
        float gI = sS * rinv;
        float s_new = (1.0f - GAMMA_S) * s_I[id] * __expf(old_b - new_b) + GAMMA_S * gI;
        float denom = s_new + EPSV;
        float loss = s1 / denom * rinv;
        float grad = logf(s_new) + new_b + RHO - s2 / denom * rinv;
        float gcl = fminf(fmaxf(grad, -GRAD_CLIP), GRAD_CLIP);
        float u_new = (1.0f - GAMMA_U) * u_I[id] + GAMMA_U * gcl;
        float eta = eta_from(ep, mep);
        float tau_new = fminf(fmaxf(tau - eta * u_new, TAU_MINV), TAU_MAXV);

        out[i] = gI;
        out[2 * B_SZ + i] = grad;
        g_loss_I[i] = loss;
        const size_t SB = 4 * B_SZ + 3;
        out[SB + (size_t)id] = s_new;
        out[SB + 2 * (size_t)N + id] = u_new;
        out[SB + 4 * (size_t)N + id] = new_b;
        out[SB + 6 * (size_t)N + id] = tau_new;
    }
}

// Column pass: two-pass branchless (pass1 raw max, pass2 exp sums; pass2 hits L2).
__global__ __launch_bounds__(1024) void col_kernel(
        const float* __restrict__ tau_T, const float* __restrict__ b_T,
        const float* __restrict__ s_T, const float* __restrict__ u_T,
        const int* __restrict__ text_ids,
        const int* __restrict__ ep, const int* __restrict__ mep,
        float* __restrict__ out, int N) {
    const int tx = threadIdx.x;  // 0..31 column lane
    const int ty = threadIdx.y;  // 0..31 row stripe
    const int j = blockIdx.x * 32 + tx;
    const int id = text_ids[j];
    const float tau = tau_T[id];
    const float inv_tau = 1.0f / tau;
    const float diag = g_sim[(size_t)j * B_SZ + j];
    const float old_b = b_T[id];

    __shared__ float red[32][33];
    __shared__ float nb[32];

    // pass 1: raw column max, unroll 4 (MLP 4)
    float mraw = -FLT_MAX;
    for (int r0 = ty; r0 < B_SZ; r0 += 128) {
        float v0 = g_sim[(size_t)(r0      ) * B_SZ + j];
        float v1 = g_sim[(size_t)(r0 + 32 ) * B_SZ + j];
        float v2 = g_sim[(size_t)(r0 + 64 ) * B_SZ + j];
        float v3 = g_sim[(size_t)(r0 + 96 ) * B_SZ + j];
        mraw = fmaxf(mraw, fmaxf(fmaxf(v0, v1), fmaxf(v2, v3)));
    }
    red[ty][tx] = mraw;
    __syncthreads();
    if (ty == 0) {
        float M = red[0][tx];
#pragma unroll
        for (int k = 1; k < 32; k++) M = fmaxf(M, red[k][tx]);
        nb[tx] = fmaxf((M - diag) * inv_tau, old_b);
    }
    __syncthreads();
    const float new_b = nb[tx];

    // pass 2: exp sums, unroll 4
    float S = 0.f, E1 = 0.f, E2 = 0.f;
    for (int r0 = ty; r0 < B_SZ; r0 += 128) {
        float v0 = g_sim[(size_t)(r0      ) * B_SZ + j];
        float v1 = g_sim[(size_t)(r0 + 32 ) * B_SZ + j];
        float v2 = g_sim[(size_t)(r0 + 64 ) * B_SZ + j];
        float v3 = g_sim[(size_t)(r0 + 96 ) * B_SZ + j];
#pragma unroll
        for (int q = 0; q < 4; q++) {
            float v = (q == 0) ? v0 : (q == 1) ? v1 : (q == 2) ? v2 : v3;
            float d = v - diag;
            float x = d * inv_tau;
            float e = __expf(x - new_b);
            S += e; E1 += e * d; E2 += e * x;
        }
    }
    __shared__ float sS[32][33], s1m[32][33], s2m[32][33];
    sS[ty][tx] = S; s1m[ty][tx] = E1; s2m[ty][tx] = E2;
    __syncthreads();

    if (ty == 0) {
        float Ss = 0.f, e1 = 0.f, e2 = 0.f;
#pragma unroll
        for (int k = 0; k < 32; k++) {
            Ss += sS[k][tx]; e1 += s1m[k][tx]; e2 += s2m[k][tx];
        }
        const float rinv = 1.0f / (float)(B_SZ - 1);
        float gT = Ss * rinv;
        float s_new = (1.0f - GAMMA_S) * s_T[id] * __expf(old_b - new_b) + GAMMA_S * gT;
        float denom = s_new + EPSV;
        float loss = e1 / denom * rinv;
        float grad = logf(s_new) + new_b + RHO - e2 / denom * rinv;
        float gcl = fminf(fmaxf(grad, -GRAD_CLIP), GRAD_CLIP);
        float u_new = (1.0f - GAMMA_U) * u_T[id] + GAMMA_U * gcl;
        float eta = eta_from(ep, mep);
        float tau_new = fminf(fmaxf(tau - eta * u_new, TAU_MINV), TAU_MAXV);

        out[B_SZ + j] = gT;
        out[3 * B_SZ + j] = grad;
        g_loss_T[j] = loss;
        const size_t SB = 4 * B_SZ + 3;
        out[SB + (size_t)N + id] = s_new;
        out[SB + 3 * (size_t)N + id] = u_new;
        out[SB + 5 * (size_t)N + id] = new_b;
        out[SB + 7 * (size_t)N + id] = tau_new;
    }
}

__global__ void finalize_kernel(const float* __restrict__ tau_I, const float* __restrict__ tau_T,
                                const int* __restrict__ iid, const int* __restrict__ tid_,
                                float* __restrict__ out) {
    const int t = threadIdx.x;  // 1024
    float lI = 0, lT = 0, tI = 0, tT = 0;
    for (int i = t; i < B_SZ; i += 1024) {
        lI += g_loss_I[i];
        lT += g_loss_T[i];
        tI += tau_I[iid[i]];
        tT += tau_T[tid_[i]];
    }
    lI = warpSum(lI); lT = warpSum(lT); tI = warpSum(tI); tT = warpSum(tT);
    __shared__ float sh[32][4];
    if ((t & 31) == 0) {
        int w = t >> 5;
        sh[w][0] = lI; sh[w][1] = lT; sh[w][2] = tI; sh[w][3] = tT;
    }
    __syncthreads();
    if (t == 0) {
        float a = 0, b = 0, c = 0, d = 0;
        for (int w = 0; w < 32; w++) { a += sh[w][0]; b += sh[w][1]; c += sh[w][2]; d += sh[w][3]; }
        const float invB = 1.0f / (float)B_SZ;
        out[4 * B_SZ + 0] = a * invB + b * invB;
        out[4 * B_SZ + 1] = c * invB;
        out[4 * B_SZ + 2] = d * invB;
    }
}

extern "C" void kernel_launch(void* const* d_in, const int* in_sizes, int n_in,
                              void* d_out, int out_size) {
    const float* imf   = (const float*)d_in[0];
    const float* txf   = (const float*)d_in[1];
    const float* s_I   = (const float*)d_in[2];
    const float* s_T   = (const float*)d_in[3];
    const float* tau_I = (const float*)d_in[4];
    const float* tau_T = (const float*)d_in[5];
    const float* u_I   = (const float*)d_in[6];
    const float* u_T   = (const float*)d_in[7];
    const float* b_I   = (const float*)d_in[8];
    const float* b_T   = (const float*)d_in[9];
    const int* iid     = (const int*)d_in[10];
    const int* tid     = (const int*)d_in[11];
    const int* ep      = (const int*)d_in[12];
    const int* mep     = (const int*)d_in[13];
    float* out = (float*)d_out;
    const int N = in_sizes[2];  // 2,900,000

    cudaFuncSetAttribute(gemm_fp16, cudaFuncAttributeMaxDynamicSharedMemorySize,
                         NSTAGE * BUF_B);

    // 1) split-convert + bulk state copy (fused)
    convert_copy_kernel<<<2048, 256>>>(imf, txf, s_I, s_T, u_I, u_T, b_I, b_T,
                                       tau_I, tau_T, out + 4 * B_SZ + 3, N);

    // 2) 3xFP16 mma.sync GEMM (3-stage cp.async, 1 sync/chunk) -> g_sim
    gemm_fp16<<<dim3(B_SZ / 128, B_SZ / 128), 256, NSTAGE * BUF_B>>>();

    // 3) row (image) pass
    row_kernel<<<B_SZ, 256>>>(tau_I, b_I, s_I, u_I, iid, ep, mep, out, N);

    // 4) column (text) pass
    col_kernel<<<B_SZ / 32, dim3(32, 32)>>>(tau_T, b_T, s_T, u_T, tid, ep, mep, out, N);

    // 5) scalars
    finalize_kernel<<<1, 1024>>>(tau_I, tau_T, iid, tid, out);
}